// round 2
// baseline (speedup 1.0000x reference)
#include <cuda_runtime.h>
#include <cuda_bf16.h>
#include <cstdint>

#define BB 4
#define TT 2048
#define DD 1024
#define BT 8192
#define HDIM 64
#define MH 4096
#define N1 3072
#define N3 8192
#define LN_EPS 1e-6f
#define GN_EPS 1e-5f
#define RMS_EPS 1e-8f

__device__ float g_params[BB * 6 * DD];
__device__ float g_wpart[6 * 64];
__device__ float g_wsinv[6];
__device__ __nv_bfloat16 g_WQ1[N1 * DD];
__device__ __nv_bfloat16 g_WQo[DD * DD];
__device__ __nv_bfloat16 g_WQg[N3 * DD];
__device__ __nv_bfloat16 g_WQd[DD * MH];
__device__ __nv_bfloat16 g_Aq[BT * DD];
__device__ float g_rowscale[BT];
__device__ __nv_bfloat16 g_HQ[(size_t)BT * MH];
__device__ float g_hscale[BT];
__device__ float g_L1[(size_t)BT * N1];
__device__ float g_H[(size_t)BT * DD];
__device__ float g_X2[(size_t)BT * DD];
__device__ float g_L3[(size_t)BT * N3];
__device__ float g_aggA[BB * 32 * DD];
__device__ float g_aggB[BB * 32 * DD];
__device__ float g_carry[BB * 32 * DD];

__device__ __forceinline__ float sigf(float x) { return 1.f / (1.f + expf(-x)); }
__device__ __forceinline__ float siluf(float x) { return x / (1.f + expf(-x)); }

__device__ __forceinline__ float bsum(float v, float* sm) {
#pragma unroll
    for (int o = 16; o; o >>= 1) v += __shfl_xor_sync(0xffffffffu, v, o);
    if ((threadIdx.x & 31) == 0) sm[threadIdx.x >> 5] = v;
    __syncthreads();
    v = sm[threadIdx.x & 7];
#pragma unroll
    for (int o = 4; o; o >>= 1) v += __shfl_xor_sync(0xffffffffu, v, o);
    return v;
}
__device__ __forceinline__ float bmax(float v, float* sm) {
#pragma unroll
    for (int o = 16; o; o >>= 1) v = fmaxf(v, __shfl_xor_sync(0xffffffffu, v, o));
    if ((threadIdx.x & 31) == 0) sm[threadIdx.x >> 5] = v;
    __syncthreads();
    v = sm[threadIdx.x & 7];
#pragma unroll
    for (int o = 4; o; o >>= 1) v = fmaxf(v, __shfl_xor_sync(0xffffffffu, v, o));
    return v;
}
__device__ __forceinline__ __nv_bfloat16 qv(float t) {
    float r = rintf(t);
    r = fminf(fmaxf(r, -128.f), 127.f);
    return __float2bfloat16(r);
}

// params = silu(c) @ adaln_w.T + b
__global__ void k_adaln(const float* __restrict__ c, const float* __restrict__ w,
                        const float* __restrict__ bias) {
    __shared__ float sc[DD];
    int b = blockIdx.y, tid = threadIdx.x;
    for (int k = tid; k < DD; k += 256) { float v = c[b * DD + k]; sc[k] = v / (1.f + expf(-v)); }
    __syncthreads();
    int wid = tid >> 5, l = tid & 31;
    int n = blockIdx.x * 8 + wid;
    const float4* wr = (const float4*)(w + (size_t)n * DD);
    float s = 0.f;
    for (int k4 = l; k4 < 256; k4 += 32) {
        float4 v = wr[k4];
        s += v.x * sc[k4 * 4] + v.y * sc[k4 * 4 + 1] + v.z * sc[k4 * 4 + 2] + v.w * sc[k4 * 4 + 3];
    }
#pragma unroll
    for (int o = 16; o; o >>= 1) s += __shfl_xor_sync(0xffffffffu, s, o);
    if (l == 0) g_params[b * 6 * DD + n] = s + bias[n];
}

__global__ void k_wabs(const float* w0, const float* w1, const float* w2,
                       const float* w3, const float* w4, const float* w5) {
    int mid = blockIdx.x >> 6, part = blockIdx.x & 63;
    const float* w; int n;
    switch (mid) {
        case 0: w = w0; n = DD * DD; break;
        case 1: w = w1; n = DD * DD; break;
        case 2: w = w2; n = DD * DD; break;
        case 3: w = w3; n = DD * DD; break;
        case 4: w = w4; n = N3 * DD; break;
        default: w = w5; n = DD * MH; break;
    }
    float s = 0.f;
    for (int i = part * 256 + threadIdx.x; i < n; i += 64 * 256) s += fabsf(w[i]);
    __shared__ float sm[8];
#pragma unroll
    for (int o = 16; o; o >>= 1) s += __shfl_xor_sync(0xffffffffu, s, o);
    if ((threadIdx.x & 31) == 0) sm[threadIdx.x >> 5] = s;
    __syncthreads();
    if (threadIdx.x == 0) {
        float t = 0.f;
        for (int i = 0; i < 8; i++) t += sm[i];
        g_wpart[blockIdx.x] = t;
    }
}
__global__ void k_wfin() {
    int t = threadIdx.x;
    if (t < 6) {
        float s = 0.f;
        for (int i = 0; i < 64; i++) s += g_wpart[t * 64 + i];
        const float cnt[6] = {1048576.f, 1048576.f, 1048576.f, 1048576.f, 8388608.f, 4194304.f};
        g_wsinv[t] = fmaxf(s / cnt[t], 1e-5f);
    }
}
__global__ void k_quantw(const float* __restrict__ w, int wsid, int dsel, int doff) {
    int i = blockIdx.x * 256 + threadIdx.x;
    __nv_bfloat16* dst = (dsel == 0) ? g_WQ1 : (dsel == 1) ? g_WQo : (dsel == 2) ? g_WQg : g_WQd;
    float ws = 1.f / g_wsinv[wsid];
    float q = rintf(w[i] * ws);
    q = fminf(1.f, fmaxf(-1.f, q));
    dst[doff + i] = __float2bfloat16(q);
}

// LN + modulate (+optional residual-add using g_H) + RMS + act quant
__global__ void k_lnmq(const float* __restrict__ xin, int shift_off, int scale_off, int mode) {
    __shared__ float red[4][8];
    int m = blockIdx.x, b = m >> 11, tid = threadIdx.x;
    float4 v = ((const float4*)(xin + (size_t)m * DD))[tid];
    if (mode) {
        float4 av = ((const float4*)(g_H + (size_t)m * DD))[tid];
        float4 gm = ((const float4*)(g_params + (size_t)b * 6 * DD + 2 * DD))[tid];
        v.x += gm.x * av.x; v.y += gm.y * av.y; v.z += gm.z * av.z; v.w += gm.w * av.w;
        ((float4*)(g_X2 + (size_t)m * DD))[tid] = v;
    }
    float S1 = bsum(v.x + v.y + v.z + v.w, red[0]);
    float S2 = bsum(v.x * v.x + v.y * v.y + v.z * v.z + v.w * v.w, red[1]);
    float mu = S1 * (1.f / DD);
    float rstd = rsqrtf(S2 * (1.f / DD) - mu * mu + LN_EPS);
    float4 sh = ((const float4*)(g_params + (size_t)b * 6 * DD + shift_off))[tid];
    float4 sc = ((const float4*)(g_params + (size_t)b * 6 * DD + scale_off))[tid];
    float4 mo;
    mo.x = (v.x - mu) * rstd * (1.f + sc.x) + sh.x;
    mo.y = (v.y - mu) * rstd * (1.f + sc.y) + sh.y;
    mo.z = (v.z - mu) * rstd * (1.f + sc.z) + sh.z;
    mo.w = (v.w - mu) * rstd * (1.f + sc.w) + sh.w;
    float Q2 = bsum(mo.x * mo.x + mo.y * mo.y + mo.z * mo.z + mo.w * mo.w, red[2]);
    float AM = bmax(fmaxf(fmaxf(fabsf(mo.x), fabsf(mo.y)), fmaxf(fabsf(mo.z), fabsf(mo.w))), red[3]);
    float rrms = rsqrtf(Q2 * (1.f / DD) + RMS_EPS);
    float clipm = fmaxf(AM * rrms, 1e-5f);
    if (tid == 0) g_rowscale[m] = clipm * (1.f / 127.f);
    float kk = rrms * 127.f / clipm;
    __nv_bfloat162 p0, p1;
    p0.x = qv(mo.x * kk); p0.y = qv(mo.y * kk);
    p1.x = qv(mo.z * kk); p1.y = qv(mo.w * kk);
    __nv_bfloat162* aq = (__nv_bfloat162*)(g_Aq + (size_t)m * DD);
    aq[tid * 2] = p0; aq[tid * 2 + 1] = p1;
}

__global__ void k_gatefi() {
    int idx = blockIdx.x * 256 + threadIdx.x;
    int m = idx >> 10, d = idx & (DD - 1);
    float* pI = g_L1 + (size_t)m * N1 + d;
    float* pF = pI + DD;
    float il = *pI, fl = *pF;
    float f = sigf(fl);
    *pI = siluf(il) * (1.f - f);
    *pF = f;
}

__global__ void k_scan1() {
    int u = blockIdx.x * 256 + threadIdx.x;
    int d = u & (DD - 1), cdx = (u >> 10) & 31, b = u >> 15;
    const float* base = g_L1 + (size_t)(b * TT + cdx * 64) * N1;
    float A = 1.f, Bv = 0.f;
#pragma unroll 4
    for (int t = 0; t < 64; t++) {
        float f = base[(size_t)t * N1 + DD + d];
        float iv = base[(size_t)t * N1 + d];
        A *= f;
        Bv = fmaf(Bv, f, iv);
    }
    int o = (b * 32 + cdx) * DD + d;
    g_aggA[o] = A; g_aggB[o] = Bv;
}
__global__ void k_scanc() {
    int v = blockIdx.x * 256 + threadIdx.x;
    int b = v >> 10, d = v & (DD - 1);
    float carry = 0.f;
    for (int cdx = 0; cdx < 32; cdx++) {
        int o = (b * 32 + cdx) * DD + d;
        g_carry[o] = carry;
        carry = fmaf(g_aggA[o], carry, g_aggB[o]);
    }
}
__global__ void k_scan2() {
    int u = blockIdx.x * 256 + threadIdx.x;
    int d = u & (DD - 1), cdx = (u >> 10) & 31, b = u >> 15;
    const float* base = g_L1 + (size_t)(b * TT + cdx * 64) * N1;
    float h = g_carry[(b * 32 + cdx) * DD + d];
#pragma unroll 4
    for (int t = 0; t < 64; t++) {
        float f = base[(size_t)t * N1 + DD + d];
        float iv = base[(size_t)t * N1 + d];
        h = fmaf(h, f, iv);
        g_H[(size_t)(b * TT + cdx * 64 + t) * DD + d] = h;
    }
}

__global__ void k_outgate(const float* __restrict__ gnw) {
    __shared__ float red[2][8];
    __shared__ float gsh[HDIM];
    int m = blockIdx.x, tid = threadIdx.x, w = tid >> 5, l = tid & 31;
    if (tid < HDIM) gsh[tid] = gnw[tid];
    __syncthreads();
    const float* hrow = g_H + (size_t)m * DD;
    const float* grow = g_L1 + (size_t)m * N1 + 2 * DD;
    float h[4], gv[4];
#pragma unroll
    for (int e = 0; e < 4; e++) {
        int n = w * 128 + e * 32 + l;
        h[e] = hrow[n]; gv[e] = grow[n];
    }
    float sA = h[0] * h[0] + h[1] * h[1];
    float sB = h[2] * h[2] + h[3] * h[3];
#pragma unroll
    for (int o = 16; o; o >>= 1) {
        sA += __shfl_xor_sync(0xffffffffu, sA, o);
        sB += __shfl_xor_sync(0xffffffffu, sB, o);
    }
    float rmsA = rsqrtf(sA * (1.f / HDIM) + GN_EPS);
    float rmsB = rsqrtf(sB * (1.f / HDIM) + GN_EPS);
    float ov[4], q2 = 0.f, am = 0.f;
#pragma unroll
    for (int e = 0; e < 4; e++) {
        int n = w * 128 + e * 32 + l;
        float r = (e < 2) ? rmsA : rmsB;
        float o = h[e] * r * gsh[n & (HDIM - 1)] * (gv[e] * sigf(gv[e]));
        ov[e] = o; q2 += o * o; am = fmaxf(am, fabsf(o));
    }
    float Q2 = bsum(q2, red[0]);
    float AM = bmax(am, red[1]);
    float rrms = rsqrtf(Q2 * (1.f / DD) + RMS_EPS);
    float clipm = fmaxf(AM * rrms, 1e-5f);
    if (tid == 0) g_rowscale[m] = clipm * (1.f / 127.f);
    float kk = rrms * 127.f / clipm;
#pragma unroll
    for (int e = 0; e < 4; e++) {
        int n = w * 128 + e * 32 + l;
        g_Aq[(size_t)m * DD + n] = qv(ov[e] * kk);
    }
}

__global__ void k_mlpact() {
    __shared__ float red[2][8];
    int m = blockIdx.x, tid = threadIdx.x;
    const float4* row = (const float4*)(g_L3 + (size_t)m * N3);
    float4 hv[4];
    float q2 = 0.f, am = 0.f;
#pragma unroll
    for (int k = 0; k < 4; k++) {
        float4 ga = row[tid + k * 256];
        float4 yy = row[tid + k * 256 + 1024];
        float4 o;
        o.x = siluf(ga.x) * yy.x; o.y = siluf(ga.y) * yy.y;
        o.z = siluf(ga.z) * yy.z; o.w = siluf(ga.w) * yy.w;
        hv[k] = o;
        q2 += o.x * o.x + o.y * o.y + o.z * o.z + o.w * o.w;
        am = fmaxf(am, fmaxf(fmaxf(fabsf(o.x), fabsf(o.y)), fmaxf(fabsf(o.z), fabsf(o.w))));
    }
    float Q2 = bsum(q2, red[0]);
    float AM = bmax(am, red[1]);
    float rrms = rsqrtf(Q2 * (1.f / MH) + RMS_EPS);
    float clipm = fmaxf(AM * rrms, 1e-5f);
    if (tid == 0) g_hscale[m] = clipm * (1.f / 127.f);
    float kk = rrms * 127.f / clipm;
    __nv_bfloat162* out = (__nv_bfloat162*)(g_HQ + (size_t)m * MH);
#pragma unroll
    for (int k = 0; k < 4; k++) {
        int j4 = tid + k * 256;
        __nv_bfloat162 p0, p1;
        p0.x = qv(hv[k].x * kk); p0.y = qv(hv[k].y * kk);
        p1.x = qv(hv[k].z * kk); p1.y = qv(hv[k].w * kk);
        out[j4 * 2] = p0; out[j4 * 2 + 1] = p1;
    }
}

__global__ void k_final(float* __restrict__ out) {
    int idx = blockIdx.x * 256 + threadIdx.x;
    int m = idx >> 10, n = idx & (DD - 1), b = m >> 11;
    out[idx] = g_X2[idx] + g_params[(size_t)b * 6 * DD + 5 * DD + n] * g_H[idx];
}

// ---- bf16 tensor-core GEMM: C[M,N] = A[M,K] @ B[N,K]^T, scaled epilogue ----
__device__ __forceinline__ void mma16816(float* c, const uint32_t* a, const uint32_t* b) {
    asm volatile(
        "mma.sync.aligned.m16n8k16.row.col.f32.bf16.bf16.f32 "
        "{%0,%1,%2,%3}, {%4,%5,%6,%7}, {%8,%9}, {%0,%1,%2,%3};\n"
        : "+f"(c[0]), "+f"(c[1]), "+f"(c[2]), "+f"(c[3])
        : "r"(a[0]), "r"(a[1]), "r"(a[2]), "r"(a[3]), "r"(b[0]), "r"(b[1]));
}
#define CP16(dst, src) \
    asm volatile("cp.async.cg.shared.global [%0], [%1], 16;\n" ::"r"(dst), "l"(src))

__global__ void __launch_bounds__(256, 1)
k_gemm(int asel, int bsel, int csel, int rssel, int wsbase, int nshift, int N, int K) {
    const __nv_bfloat16* A = asel ? g_HQ : g_Aq;
    const __nv_bfloat16* Bw = (bsel == 0) ? g_WQ1 : (bsel == 1) ? g_WQo : (bsel == 2) ? g_WQg : g_WQd;
    float* C = (csel == 0) ? g_L1 : (csel == 1) ? g_H : g_L3;
    const float* rsc = rssel ? g_hscale : g_rowscale;

    __shared__ __nv_bfloat16 As[2][128 * 40];
    __shared__ __nv_bfloat16 Bs[2][128 * 40];

    int tid = threadIdx.x;
    int bm = blockIdx.y << 7, bn = blockIdx.x << 7;
    int lrow = tid >> 2, lcol = (tid & 3) << 3;
    const __nv_bfloat16* ag = A + (size_t)(bm + lrow) * K + lcol;
    const __nv_bfloat16* bg = Bw + (size_t)(bn + lrow) * K + lcol;

    int w = tid >> 5, l = tid & 31;
    int wm = (w >> 2) << 6, wn = (w & 3) << 5;
    int g = l >> 2, tg = l & 3;

    float acc[4][4][4] = {};

    CP16((uint32_t)__cvta_generic_to_shared(&As[0][lrow * 40 + lcol]), ag);
    CP16((uint32_t)__cvta_generic_to_shared(&As[0][(lrow + 64) * 40 + lcol]), ag + (size_t)64 * K);
    CP16((uint32_t)__cvta_generic_to_shared(&Bs[0][lrow * 40 + lcol]), bg);
    CP16((uint32_t)__cvta_generic_to_shared(&Bs[0][(lrow + 64) * 40 + lcol]), bg + (size_t)64 * K);
    asm volatile("cp.async.commit_group;\n" ::: "memory");

    int NT = K >> 5;
    for (int kt = 0; kt < NT; kt++) {
        asm volatile("cp.async.wait_group 0;\n" ::: "memory");
        __syncthreads();
        int buf = kt & 1;
        if (kt + 1 < NT) {
            int kk = (kt + 1) << 5, nb = buf ^ 1;
            CP16((uint32_t)__cvta_generic_to_shared(&As[nb][lrow * 40 + lcol]), ag + kk);
            CP16((uint32_t)__cvta_generic_to_shared(&As[nb][(lrow + 64) * 40 + lcol]), ag + (size_t)64 * K + kk);
            CP16((uint32_t)__cvta_generic_to_shared(&Bs[nb][lrow * 40 + lcol]), bg + kk);
            CP16((uint32_t)__cvta_generic_to_shared(&Bs[nb][(lrow + 64) * 40 + lcol]), bg + (size_t)64 * K + kk);
            asm volatile("cp.async.commit_group;\n" ::: "memory");
        }
        const __nv_bfloat16* Ab = As[buf];
        const __nv_bfloat16* Bb = Bs[buf];
#pragma unroll
        for (int ks = 0; ks < 2; ks++) {
            int k0 = ks * 16 + tg * 2;
            uint32_t af[4][4], bf[4][2];
#pragma unroll
            for (int mt = 0; mt < 4; mt++) {
                int r0 = wm + mt * 16 + g;
                af[mt][0] = *(const uint32_t*)&Ab[r0 * 40 + k0];
                af[mt][1] = *(const uint32_t*)&Ab[(r0 + 8) * 40 + k0];
                af[mt][2] = *(const uint32_t*)&Ab[r0 * 40 + k0 + 8];
                af[mt][3] = *(const uint32_t*)&Ab[(r0 + 8) * 40 + k0 + 8];
            }
#pragma unroll
            for (int nt = 0; nt < 4; nt++) {
                int r0 = wn + nt * 8 + g;
                bf[nt][0] = *(const uint32_t*)&Bb[r0 * 40 + k0];
                bf[nt][1] = *(const uint32_t*)&Bb[r0 * 40 + k0 + 8];
            }
#pragma unroll
            for (int mt = 0; mt < 4; mt++)
#pragma unroll
                for (int nt = 0; nt < 4; nt++) mma16816(acc[mt][nt], af[mt], bf[nt]);
        }
        __syncthreads();
    }

#pragma unroll
    for (int mt = 0; mt < 4; mt++) {
        int r0 = bm + wm + mt * 16 + g;
        float s0 = rsc[r0], s1 = rsc[r0 + 8];
#pragma unroll
        for (int nt = 0; nt < 4; nt++) {
            int c0 = bn + wn + nt * 8 + tg * 2;
            float cs = g_wsinv[wsbase + (c0 >> nshift)];
            float* p0 = C + (size_t)r0 * N + c0;
            float* p1 = C + (size_t)(r0 + 8) * N + c0;
            p0[0] = acc[mt][nt][0] * s0 * cs;
            p0[1] = acc[mt][nt][1] * s0 * cs;
            p1[0] = acc[mt][nt][2] * s1 * cs;
            p1[1] = acc[mt][nt][3] * s1 * cs;
        }
    }
}

extern "C" void kernel_launch(void* const* d_in, const int* in_sizes, int n_in,
                              void* d_out, int out_size) {
    const float* x = (const float*)d_in[0];
    const float* c = (const float*)d_in[1];
    const float* adaln_w = (const float*)d_in[2];
    const float* adaln_b = (const float*)d_in[3];
    const float* wi = (const float*)d_in[4];
    const float* wf = (const float*)d_in[5];
    const float* wg = (const float*)d_in[6];
    const float* gnorm_w = (const float*)d_in[7];
    const float* wo = (const float*)d_in[8];
    const float* gate_w = (const float*)d_in[9];
    const float* down_w = (const float*)d_in[10];
    float* out = (float*)d_out;

    // adaLN params
    k_adaln<<<dim3(768, 4), 256>>>(c, adaln_w, adaln_b);
    // weight scales + ternary quant
    k_wabs<<<384, 256>>>(wi, wf, wg, wo, gate_w, down_w);
    k_wfin<<<1, 32>>>();
    k_quantw<<<4096, 256>>>(wi, 0, 0, 0);
    k_quantw<<<4096, 256>>>(wf, 1, 0, 1024 * 1024);
    k_quantw<<<4096, 256>>>(wg, 2, 0, 2 * 1024 * 1024);
    k_quantw<<<4096, 256>>>(wo, 3, 1, 0);
    k_quantw<<<32768, 256>>>(gate_w, 4, 2, 0);
    k_quantw<<<16384, 256>>>(down_w, 5, 3, 0);
    // attention branch
    k_lnmq<<<BT, 256>>>(x, 0, DD, 0);
    k_gemm<<<dim3(24, 64), 256>>>(0, 0, 0, 0, 0, 10, N1, DD);   // i|f|g
    k_gatefi<<<32768, 256>>>();
    k_scan1<<<512, 256>>>();
    k_scanc<<<16, 256>>>();
    k_scan2<<<512, 256>>>();
    k_outgate<<<BT, 256>>>(gnorm_w);
    k_gemm<<<dim3(8, 64), 256>>>(0, 1, 1, 0, 3, 30, DD, DD);    // out proj -> g_H
    // residual + MLP branch
    k_lnmq<<<BT, 256>>>(x, 3 * DD, 4 * DD, 1);
    k_gemm<<<dim3(64, 64), 256>>>(0, 2, 2, 0, 4, 30, N3, DD);   // gate proj -> g_L3
    k_mlpact<<<BT, 256>>>();
    k_gemm<<<dim3(8, 64), 256>>>(1, 3, 1, 1, 5, 30, DD, MH);    // down proj -> g_H
    k_final<<<32768, 256>>>(out);
}